// round 12
// baseline (speedup 1.0000x reference)
#include <cuda_runtime.h>
#include <cuda_bf16.h>

#define N_NODES    200000
#define NUM_GRAPHS 2000
#define VOCAB      10000
#define D          64
#define NT         4     // nodes per thread (T1 kernel)
#define MAX_E      1600000
#define SCAN_B     256
#define NB_SCAN    ((N_NODES + SCAN_B - 1) / SCAN_B)   // 782

// ---------------- scratch (static device globals; no allocation) ------------
__device__ float g_T1  [(size_t)VOCAB * D];     // embed_table @ W1 (unscaled)
__device__ float g_bufA[(size_t)N_NODES * D];   // layer-2 ts = dinv*(h@W2)
__device__ float g_bufB[(size_t)N_NODES * D];   // h (layer-1 activations)
__device__ float g_dinv[N_NODES];
__device__ int   g_deg [N_NODES];
__device__ int   g_start[N_NODES];              // CSR row offsets (by dst)
__device__ int   g_cursor[N_NODES];
__device__ int   g_csr[MAX_E];                  // src indices bucketed by dst
__device__ int   g_bsum[NB_SCAN];
__device__ float g_gsum[NUM_GRAPHS * D];
__device__ float g_gcnt[NUM_GRAPHS];

// vectorized no-return global reduction (sm_90+)
__device__ __forceinline__ void red_add_v4(float* addr, float4 v) {
    asm volatile("red.global.add.v4.f32 [%0], {%1, %2, %3, %4};"
                 :: "l"(addr), "f"(v.x), "f"(v.y), "f"(v.z), "f"(v.w)
                 : "memory");
}

// ---------------- packed f32x2 helpers (sm_103a FFMA2 path) -----------------
__device__ __forceinline__ unsigned long long pack2(float v) {
    unsigned long long r;
    asm("mov.b64 %0, {%1, %1};" : "=l"(r) : "f"(v));
    return r;
}
__device__ __forceinline__ void ffma2(unsigned long long& d,
                                      unsigned long long a,
                                      unsigned long long b) {
    asm("fma.rn.f32x2 %0, %1, %2, %0;" : "+l"(d) : "l"(a), "l"(b));
}
__device__ __forceinline__ void add2(unsigned long long& d,
                                     unsigned long long a) {
    asm("add.rn.f32x2 %0, %0, %1;" : "+l"(d) : "l"(a));
}
__device__ __forceinline__ void mul2(unsigned long long& d,
                                     unsigned long long a) {
    asm("mul.rn.f32x2 %0, %0, %1;" : "+l"(d) : "l"(a));
}

// ---------------- init: zero deg / gsum / gcnt ------------------------------
__global__ void k_init() {
    int t = blockIdx.x * blockDim.x + threadIdx.x;
    if (t < N_NODES)        g_deg[t]  = 0;
    if (t < NUM_GRAPHS * D) g_gsum[t] = 0.0f;
    if (t < NUM_GRAPHS)     g_gcnt[t] = 0.0f;
}

// ---------------- degree (in-degree over dst) -------------------------------
__global__ void k_deg(const int* __restrict__ dst, int E) {
    int e = blockIdx.x * blockDim.x + threadIdx.x;
    if (e < E) atomicAdd(&g_deg[dst[e]], 1);
}

// ---------------- CSR build: scan + fill ------------------------------------
__global__ void k_scan1() {
    __shared__ int s[SCAN_B];
    int tid = threadIdx.x;
    int t = blockIdx.x * SCAN_B + tid;
    int v = (t < N_NODES) ? g_deg[t] : 0;
    s[tid] = v;
    __syncthreads();
    #pragma unroll
    for (int o = 1; o < SCAN_B; o <<= 1) {
        int u = (tid >= o) ? s[tid - o] : 0;
        __syncthreads();
        s[tid] += u;
        __syncthreads();
    }
    if (t < N_NODES) g_start[t] = s[tid] - v;     // exclusive
    if (tid == SCAN_B - 1) g_bsum[blockIdx.x] = s[tid];
}

__global__ void k_scan2() {
    __shared__ int s[1024];
    int tid = threadIdx.x;
    int v = (tid < NB_SCAN) ? g_bsum[tid] : 0;
    s[tid] = v;
    __syncthreads();
    #pragma unroll
    for (int o = 1; o < 1024; o <<= 1) {
        int u = (tid >= o) ? s[tid - o] : 0;
        __syncthreads();
        s[tid] += u;
        __syncthreads();
    }
    if (tid < NB_SCAN) g_bsum[tid] = s[tid] - v;  // exclusive block offsets
}

__global__ void k_scan3() {
    int t = blockIdx.x * blockDim.x + threadIdx.x;
    if (t >= N_NODES) return;
    int st = g_start[t] + g_bsum[blockIdx.x];
    g_start[t]  = st;
    g_cursor[t] = st;
    g_dinv[t]   = rsqrtf((float)(g_deg[t] + 1));  // +1 self loop
}

__global__ void k_fill(const int* __restrict__ src, const int* __restrict__ dst, int E) {
    int e = blockIdx.x * blockDim.x + threadIdx.x;
    if (e >= E) return;
    int d = dst[e];
    int pos = atomicAdd(&g_cursor[d], 1);
    g_csr[pos] = src[e];
}

// FFMA2 k-slice, 16 cols/thread (T1 kernel)
#define KSTEP2(R, COMP)                                                       \
    {                                                                         \
        const ulonglong2* wr =                                                \
            (const ulonglong2*)&Ws[(k4 * 4 + (R)) * 16 + q * 4];              \
        ulonglong2 wv0 = wr[0], wv1 = wr[1], wv2 = wr[2], wv3 = wr[3];        \
        _Pragma("unroll")                                                     \
        for (int i = 0; i < NT; i++) {                                        \
            unsigned long long hs2 = pack2(h[i].COMP);                        \
            ffma2(acc2[i][0], hs2, wv0.x);                                    \
            ffma2(acc2[i][1], hs2, wv0.y);                                    \
            ffma2(acc2[i][2], hs2, wv1.x);                                    \
            ffma2(acc2[i][3], hs2, wv1.y);                                    \
            ffma2(acc2[i][4], hs2, wv2.x);                                    \
            ffma2(acc2[i][5], hs2, wv2.y);                                    \
            ffma2(acc2[i][6], hs2, wv3.x);                                    \
            ffma2(acc2[i][7], hs2, wv3.y);                                    \
        }                                                                     \
    }

// ---------------- T1 = embed_table @ W1  (VOCAB x 64, unscaled) -------------
__global__ void __launch_bounds__(256, 2)
k_t1(const float* __restrict__ table, const float* __restrict__ W) {
    __shared__ float4 Ws[D * 16];   // W row-major: Ws[k*16 + j4]
    for (int t = threadIdx.x; t < D * 16; t += 256)
        Ws[t] = ((const float4*)W)[t];
    __syncthreads();

    int T    = blockIdx.x * 256 + threadIdx.x;
    int lane = threadIdx.x & 31;
    int q    = lane & 3;
    int r8   = lane >> 2;
    int wb   = (T >> 5) * 32;

    int n[NT];
    const float4* hrow[NT];
    #pragma unroll
    for (int i = 0; i < NT; i++) {
        n[i] = wb + r8 + i * 8;
        int ns = (n[i] < VOCAB) ? n[i] : 0;
        hrow[i] = (const float4*)(table + (size_t)ns * D);
    }

    unsigned long long acc2[NT][8];
    #pragma unroll
    for (int i = 0; i < NT; i++)
        #pragma unroll
        for (int j = 0; j < 8; j++) acc2[i][j] = 0ull;

    #pragma unroll 4
    for (int k4 = 0; k4 < 16; k4++) {
        float4 h[NT];
        #pragma unroll
        for (int i = 0; i < NT; i++) h[i] = hrow[i][k4];
        KSTEP2(0, x)
        KSTEP2(1, y)
        KSTEP2(2, z)
        KSTEP2(3, w)
    }

    #pragma unroll
    for (int i = 0; i < NT; i++) {
        if (n[i] >= VOCAB) continue;
        ulonglong2* O = (ulonglong2*)((float4*)g_T1 + (size_t)n[i] * 16 + q * 4);
        #pragma unroll
        for (int j = 0; j < 4; j++)
            O[j] = make_ulonglong2(acc2[i][2 * j], acc2[i][2 * j + 1]);
    }
}

// ---- gather layer 1: h = relu(di*(di*T1[x_i] + Σ dinv[s]*T1[x[s]]) + b1) ---
// One warp per node; manual 2-way software pipelining (R10-validated).
__global__ void __launch_bounds__(256)
k_gather1(const int* __restrict__ x, const float* __restrict__ bias) {
    int warp = (blockIdx.x * blockDim.x + threadIdx.x) >> 5;
    if (warp >= N_NODES) return;
    int lane = threadIdx.x & 31;
    int half = lane >> 4;
    int c    = lane & 15;

    int s0 = g_start[warp];
    int dg = g_deg[warp];

    float4 acc0 = make_float4(0.f, 0.f, 0.f, 0.f);
    float4 acc1 = make_float4(0.f, 0.f, 0.f, 0.f);
    int e = half;
    for (; e + 2 < dg; e += 4) {
        int sA = __ldg(&g_csr[s0 + e]);
        int sB = __ldg(&g_csr[s0 + e + 2]);
        int xA = __ldg(x + sA);
        int xB = __ldg(x + sB);
        float dA = __ldg(&g_dinv[sA]);
        float dB = __ldg(&g_dinv[sB]);
        float4 vA = ((const float4*)g_T1)[(size_t)xA * 16 + c];
        float4 vB = ((const float4*)g_T1)[(size_t)xB * 16 + c];
        acc0.x += dA * vA.x; acc0.y += dA * vA.y;
        acc0.z += dA * vA.z; acc0.w += dA * vA.w;
        acc1.x += dB * vB.x; acc1.y += dB * vB.y;
        acc1.z += dB * vB.z; acc1.w += dB * vB.w;
    }
    if (e < dg) {
        int s  = __ldg(&g_csr[s0 + e]);
        int xi = __ldg(x + s);
        float ds = __ldg(&g_dinv[s]);
        float4 v = ((const float4*)g_T1)[(size_t)xi * 16 + c];
        acc0.x += ds * v.x; acc0.y += ds * v.y;
        acc0.z += ds * v.z; acc0.w += ds * v.w;
    }
    float4 acc;
    acc.x = acc0.x + acc1.x; acc.y = acc0.y + acc1.y;
    acc.z = acc0.z + acc1.z; acc.w = acc0.w + acc1.w;

    acc.x += __shfl_down_sync(0xffffffffu, acc.x, 16);
    acc.y += __shfl_down_sync(0xffffffffu, acc.y, 16);
    acc.z += __shfl_down_sync(0xffffffffu, acc.z, 16);
    acc.w += __shfl_down_sync(0xffffffffu, acc.w, 16);

    if (half == 0) {
        float di = g_dinv[warp];
        int xi = __ldg(x + warp);
        float4 a  = ((const float4*)g_T1)[(size_t)xi * 16 + c];
        float4 bb = __ldg((const float4*)bias + c);
        float4 h;
        h.x = fmaxf(di * (di * a.x + acc.x) + bb.x, 0.f);
        h.y = fmaxf(di * (di * a.y + acc.y) + bb.y, 0.f);
        h.z = fmaxf(di * (di * a.z + acc.z) + bb.z, 0.f);
        h.w = fmaxf(di * (di * a.w + acc.w) + bb.w, 0.f);
        ((float4*)g_bufB)[(size_t)warp * 16 + c] = h;
    }
}

// ---------------- layer-2 transform: A = dinv * (h @ W2) --------------------
// Standalone warp-per-node (R11 phase-2 pattern, decoupled from the gather):
// warp stages its node's h row via one coalesced LDG.64/lane, lane l computes
// packed output cols (2l, 2l+1). 8 nodes/block; uniform work -> the single
// __syncthreads (covering the W2 smem load) has no straggler problem.
__global__ void __launch_bounds__(256)
k_t2(const float* __restrict__ W2) {
    __shared__ float4 Ws[D * 16];   // W2 row-major: Ws[k*16 + j4] (16 KB)
    __shared__ float  hs[8][D];     // 8 h rows (2 KB)

    for (int t = threadIdx.x; t < D * 16; t += 256)
        Ws[t] = ((const float4*)W2)[t];

    int w    = threadIdx.x >> 5;
    int lane = threadIdx.x & 31;
    int node = blockIdx.x * 8 + w;

    if (node < N_NODES) {
        unsigned long long hv =
            ((const unsigned long long*)g_bufB)[(size_t)node * 32 + lane];
        ((unsigned long long*)hs[w])[lane] = hv;
    }
    __syncthreads();

    if (node >= N_NODES) return;

    const unsigned long long* wp = (const unsigned long long*)Ws;
    unsigned long long a0 = 0ull, a1 = 0ull;   // 2 accumulators (shorter chain)
    #pragma unroll
    for (int k4 = 0; k4 < 16; k4++) {
        float4 hv = ((const float4*)hs[w])[k4];        // broadcast LDS.128
        ffma2(a0, pack2(hv.x), wp[(k4 * 4 + 0) * 32 + lane]);
        ffma2(a1, pack2(hv.y), wp[(k4 * 4 + 1) * 32 + lane]);
        ffma2(a0, pack2(hv.z), wp[(k4 * 4 + 2) * 32 + lane]);
        ffma2(a1, pack2(hv.w), wp[(k4 * 4 + 3) * 32 + lane]);
    }
    add2(a0, a1);
    mul2(a0, pack2(g_dinv[node]));
    ((unsigned long long*)g_bufA)[(size_t)node * 32 + lane] = a0;  // STG.64
}

// ------- gather layer 2 + pool: gsum[b] += relu(dinv*(A_i+agg)+b2) ----------
__global__ void __launch_bounds__(256)
k_gather2(const int* __restrict__ batch, const float* __restrict__ bias) {
    int warp = (blockIdx.x * blockDim.x + threadIdx.x) >> 5;
    if (warp >= N_NODES) return;
    int lane = threadIdx.x & 31;
    int half = lane >> 4;
    int c    = lane & 15;

    int s0 = g_start[warp];
    int dg = g_deg[warp];

    float4 acc0 = make_float4(0.f, 0.f, 0.f, 0.f);
    float4 acc1 = make_float4(0.f, 0.f, 0.f, 0.f);
    int e = half;
    for (; e + 2 < dg; e += 4) {
        int sA = __ldg(&g_csr[s0 + e]);
        int sB = __ldg(&g_csr[s0 + e + 2]);
        float4 vA = ((const float4*)g_bufA)[(size_t)sA * 16 + c];
        float4 vB = ((const float4*)g_bufA)[(size_t)sB * 16 + c];
        acc0.x += vA.x; acc0.y += vA.y; acc0.z += vA.z; acc0.w += vA.w;
        acc1.x += vB.x; acc1.y += vB.y; acc1.z += vB.z; acc1.w += vB.w;
    }
    if (e < dg) {
        int s = __ldg(&g_csr[s0 + e]);
        float4 v = ((const float4*)g_bufA)[(size_t)s * 16 + c];
        acc0.x += v.x; acc0.y += v.y; acc0.z += v.z; acc0.w += v.w;
    }
    float4 acc;
    acc.x = acc0.x + acc1.x; acc.y = acc0.y + acc1.y;
    acc.z = acc0.z + acc1.z; acc.w = acc0.w + acc1.w;

    acc.x += __shfl_down_sync(0xffffffffu, acc.x, 16);
    acc.y += __shfl_down_sync(0xffffffffu, acc.y, 16);
    acc.z += __shfl_down_sync(0xffffffffu, acc.z, 16);
    acc.w += __shfl_down_sync(0xffffffffu, acc.w, 16);

    if (half == 0) {
        float di = g_dinv[warp];
        int b = __ldg(batch + warp);
        float4 a  = ((const float4*)g_bufA)[(size_t)warp * 16 + c];
        float4 bb = __ldg((const float4*)bias + c);
        float4 v;
        v.x = fmaxf(di * (a.x + acc.x) + bb.x, 0.f);
        v.y = fmaxf(di * (a.y + acc.y) + bb.y, 0.f);
        v.z = fmaxf(di * (a.z + acc.z) + bb.z, 0.f);
        v.w = fmaxf(di * (a.w + acc.w) + bb.w, 0.f);
        red_add_v4(&g_gsum[b * D + c * 4], v);
        if (c == 0) atomicAdd(&g_gcnt[b], 1.0f);
    }
}

// ---------------- head: out[g] = (gsum[g]/cnt) @ Wlin + blin ----------------
__global__ void k_final(const float* __restrict__ Wlin,
                        const float* __restrict__ blin,
                        float* __restrict__ out) {
    int g = blockIdx.x * blockDim.x + threadIdx.x;
    if (g >= NUM_GRAPHS) return;
    float inv = 1.0f / fmaxf(g_gcnt[g], 1.0f);
    float a0 = blin[0], a1 = blin[1];
    #pragma unroll
    for (int j = 0; j < D; j++) {
        float v = g_gsum[g * D + j] * inv;
        a0 += v * Wlin[2 * j + 0];
        a1 += v * Wlin[2 * j + 1];
    }
    out[2 * g + 0] = a0;
    out[2 * g + 1] = a1;
}

// ---------------- launch ----------------------------------------------------
extern "C" void kernel_launch(void* const* d_in, const int* in_sizes, int n_in,
                              void* d_out, int out_size) {
    const int*   x     = (const int*)  d_in[0];
    const int*   ei    = (const int*)  d_in[1];
    const int*   batch = (const int*)  d_in[3];
    const float* table = (const float*)d_in[4];
    const float* W1    = (const float*)d_in[5];
    const float* b1    = (const float*)d_in[6];
    const float* W2    = (const float*)d_in[7];
    const float* b2    = (const float*)d_in[8];
    const float* Wlin  = (const float*)d_in[9];
    const float* blin  = (const float*)d_in[10];
    float*       out   = (float*)d_out;

    int E = in_sizes[1] / 2;
    const int* src = ei;       // edge_index[0]
    const int* dst = ei + E;   // edge_index[1]

    const int TPB = 256;
    int gbN = (N_NODES + TPB - 1) / TPB;                         // 782
    int gbE = (E + TPB - 1) / TPB;
    int gbW = (int)(((long long)N_NODES * 32 + TPB - 1) / TPB);  // warp/node
    int gbV = (VOCAB + TPB - 1) / TPB;                           // 40
    int gbT2 = (N_NODES + 7) / 8;                                // 25000

    // Fork a second branch for the CSR build (independent of T1).
    cudaStream_t s2;
    cudaEvent_t evFork, evJoin;
    cudaStreamCreateWithFlags(&s2, cudaStreamNonBlocking);
    cudaEventCreateWithFlags(&evFork, cudaEventDisableTiming);
    cudaEventCreateWithFlags(&evJoin, cudaEventDisableTiming);

    cudaEventRecord(evFork, 0);
    cudaStreamWaitEvent(s2, evFork, 0);

    // branch A (s2): CSR build + dinv
    k_init<<<gbN, TPB, 0, s2>>>();
    k_deg<<<gbE, TPB, 0, s2>>>(dst, E);
    k_scan1<<<NB_SCAN, SCAN_B, 0, s2>>>();
    k_scan2<<<1, 1024, 0, s2>>>();
    k_scan3<<<NB_SCAN, SCAN_B, 0, s2>>>();
    k_fill<<<gbE, TPB, 0, s2>>>(src, dst, E);

    // branch B (main stream): tiny vocab-level transform
    k_t1<<<gbV, TPB>>>(table, W1);                 // T1 = table @ W1

    // join
    cudaEventRecord(evJoin, s2);
    cudaStreamWaitEvent(0, evJoin, 0);

    k_gather1<<<gbW, TPB>>>(x, b1);                // B = relu(di*(di*T1[x_i]+Σ ds*T1[xs])+b1)
    k_t2<<<gbT2, TPB>>>(W2);                       // A = dinv*(B@W2), warp-per-node
    k_gather2<<<gbW, TPB>>>(batch, b2);            // gsum += relu(dinv*(A_i+ΣA_s)+b2)
    k_final<<<(NUM_GRAPHS + TPB - 1) / TPB, TPB>>>(Wlin, blin, out);

    cudaEventDestroy(evFork);
    cudaEventDestroy(evJoin);
    cudaStreamDestroy(s2);
}

// round 13
// speedup vs baseline: 1.1907x; 1.1907x over previous
#include <cuda_runtime.h>
#include <cuda_bf16.h>

#define N_NODES    200000
#define NUM_GRAPHS 2000
#define VOCAB      10000
#define D          64
#define NT         4     // nodes per thread (gemm kernels)
#define MAX_E      1600000
#define SCAN_B     256
#define NB_SCAN    ((N_NODES + SCAN_B - 1) / SCAN_B)   // 782
#define NTILE      4
#define TILE       (N_NODES / NTILE)                   // 50000

// ---------------- scratch (static device globals; no allocation) ------------
__device__ float g_T1  [(size_t)VOCAB * D];     // embed_table @ W1 (unscaled)
__device__ float g_bufA[(size_t)N_NODES * D];   // layer-2 ts = dinv*(h@W2)
__device__ float g_bufB[(size_t)N_NODES * D];   // h (layer-1 activations)
__device__ float g_dinv[N_NODES];
__device__ int   g_deg [N_NODES];
__device__ int   g_start[N_NODES];              // CSR row offsets (by dst)
__device__ int   g_cursor[N_NODES];
__device__ int   g_csr[MAX_E];                  // src indices bucketed by dst
__device__ int   g_bsum[NB_SCAN];
__device__ float g_gsum[NUM_GRAPHS * D];
__device__ float g_gcnt[NUM_GRAPHS];

// vectorized no-return global reduction (sm_90+)
__device__ __forceinline__ void red_add_v4(float* addr, float4 v) {
    asm volatile("red.global.add.v4.f32 [%0], {%1, %2, %3, %4};"
                 :: "l"(addr), "f"(v.x), "f"(v.y), "f"(v.z), "f"(v.w)
                 : "memory");
}

// ---------------- packed f32x2 helpers (sm_103a FFMA2 path) -----------------
__device__ __forceinline__ unsigned long long pack2(float v) {
    unsigned long long r;
    asm("mov.b64 %0, {%1, %1};" : "=l"(r) : "f"(v));
    return r;
}
__device__ __forceinline__ void ffma2(unsigned long long& d,
                                      unsigned long long a,
                                      unsigned long long b) {
    asm("fma.rn.f32x2 %0, %1, %2, %0;" : "+l"(d) : "l"(a), "l"(b));
}
__device__ __forceinline__ void mul2(unsigned long long& d,
                                     unsigned long long a) {
    asm("mul.rn.f32x2 %0, %0, %1;" : "+l"(d) : "l"(a));
}

// ---------------- init: zero deg / gsum / gcnt ------------------------------
__global__ void k_init() {
    int t = blockIdx.x * blockDim.x + threadIdx.x;
    if (t < N_NODES)        g_deg[t]  = 0;
    if (t < NUM_GRAPHS * D) g_gsum[t] = 0.0f;
    if (t < NUM_GRAPHS)     g_gcnt[t] = 0.0f;
}

// ---------------- degree (in-degree over dst) -------------------------------
__global__ void k_deg(const int* __restrict__ dst, int E) {
    int e = blockIdx.x * blockDim.x + threadIdx.x;
    if (e < E) atomicAdd(&g_deg[dst[e]], 1);
}

// ---------------- CSR build: scan + fill ------------------------------------
__global__ void k_scan1() {
    __shared__ int s[SCAN_B];
    int tid = threadIdx.x;
    int t = blockIdx.x * SCAN_B + tid;
    int v = (t < N_NODES) ? g_deg[t] : 0;
    s[tid] = v;
    __syncthreads();
    #pragma unroll
    for (int o = 1; o < SCAN_B; o <<= 1) {
        int u = (tid >= o) ? s[tid - o] : 0;
        __syncthreads();
        s[tid] += u;
        __syncthreads();
    }
    if (t < N_NODES) g_start[t] = s[tid] - v;     // exclusive
    if (tid == SCAN_B - 1) g_bsum[blockIdx.x] = s[tid];
}

__global__ void k_scan2() {
    __shared__ int s[1024];
    int tid = threadIdx.x;
    int v = (tid < NB_SCAN) ? g_bsum[tid] : 0;
    s[tid] = v;
    __syncthreads();
    #pragma unroll
    for (int o = 1; o < 1024; o <<= 1) {
        int u = (tid >= o) ? s[tid - o] : 0;
        __syncthreads();
        s[tid] += u;
        __syncthreads();
    }
    if (tid < NB_SCAN) g_bsum[tid] = s[tid] - v;  // exclusive block offsets
}

__global__ void k_scan3() {
    int t = blockIdx.x * blockDim.x + threadIdx.x;
    if (t >= N_NODES) return;
    int st = g_start[t] + g_bsum[blockIdx.x];
    g_start[t]  = st;
    g_cursor[t] = st;
    g_dinv[t]   = rsqrtf((float)(g_deg[t] + 1));  // +1 self loop
}

__global__ void k_fill(const int* __restrict__ src, const int* __restrict__ dst, int E) {
    int e = blockIdx.x * blockDim.x + threadIdx.x;
    if (e >= E) return;
    int d = dst[e];
    int pos = atomicAdd(&g_cursor[d], 1);
    g_csr[pos] = src[e];
}

// FFMA2 k-slice, 16 cols/thread
#define KSTEP2(R, COMP)                                                       \
    {                                                                         \
        const ulonglong2* wr =                                                \
            (const ulonglong2*)&Ws[(k4 * 4 + (R)) * 16 + q * 4];              \
        ulonglong2 wv0 = wr[0], wv1 = wr[1], wv2 = wr[2], wv3 = wr[3];        \
        _Pragma("unroll")                                                     \
        for (int i = 0; i < NT; i++) {                                        \
            unsigned long long hs2 = pack2(h[i].COMP);                        \
            ffma2(acc2[i][0], hs2, wv0.x);                                    \
            ffma2(acc2[i][1], hs2, wv0.y);                                    \
            ffma2(acc2[i][2], hs2, wv1.x);                                    \
            ffma2(acc2[i][3], hs2, wv1.y);                                    \
            ffma2(acc2[i][4], hs2, wv2.x);                                    \
            ffma2(acc2[i][5], hs2, wv2.y);                                    \
            ffma2(acc2[i][6], hs2, wv3.x);                                    \
            ffma2(acc2[i][7], hs2, wv3.y);                                    \
        }                                                                     \
    }

// ---------------- T1 = embed_table @ W1  (VOCAB x 64, unscaled) -------------
__global__ void __launch_bounds__(256, 2)
k_t1(const float* __restrict__ table, const float* __restrict__ W) {
    __shared__ float4 Ws[D * 16];   // W row-major: Ws[k*16 + j4]
    for (int t = threadIdx.x; t < D * 16; t += 256)
        Ws[t] = ((const float4*)W)[t];
    __syncthreads();

    int T    = blockIdx.x * 256 + threadIdx.x;
    int lane = threadIdx.x & 31;
    int q    = lane & 3;
    int r8   = lane >> 2;
    int wb   = (T >> 5) * 32;

    int n[NT];
    const float4* hrow[NT];
    #pragma unroll
    for (int i = 0; i < NT; i++) {
        n[i] = wb + r8 + i * 8;
        int ns = (n[i] < VOCAB) ? n[i] : 0;
        hrow[i] = (const float4*)(table + (size_t)ns * D);
    }

    unsigned long long acc2[NT][8];
    #pragma unroll
    for (int i = 0; i < NT; i++)
        #pragma unroll
        for (int j = 0; j < 8; j++) acc2[i][j] = 0ull;

    #pragma unroll 4
    for (int k4 = 0; k4 < 16; k4++) {
        float4 h[NT];
        #pragma unroll
        for (int i = 0; i < NT; i++) h[i] = hrow[i][k4];
        KSTEP2(0, x)
        KSTEP2(1, y)
        KSTEP2(2, z)
        KSTEP2(3, w)
    }

    #pragma unroll
    for (int i = 0; i < NT; i++) {
        if (n[i] >= VOCAB) continue;
        ulonglong2* O = (ulonglong2*)((float4*)g_T1 + (size_t)n[i] * 16 + q * 4);
        #pragma unroll
        for (int j = 0; j < 4; j++)
            O[j] = make_ulonglong2(acc2[i][2 * j], acc2[i][2 * j + 1]);
    }
}

// ---- gather layer 1 (node tile [lo,hi)):
//      h = relu(di*(di*T1[x_i] + Σ dinv[s]*T1[x[s]]) + b1)
__global__ void __launch_bounds__(256)
k_gather1(const int* __restrict__ x, const float* __restrict__ bias,
          int lo, int hi) {
    int warp = lo + ((blockIdx.x * blockDim.x + threadIdx.x) >> 5);
    if (warp >= hi) return;
    int lane = threadIdx.x & 31;
    int half = lane >> 4;
    int c    = lane & 15;

    int s0 = g_start[warp];
    int dg = g_deg[warp];

    float4 acc0 = make_float4(0.f, 0.f, 0.f, 0.f);
    float4 acc1 = make_float4(0.f, 0.f, 0.f, 0.f);
    int e = half;
    for (; e + 2 < dg; e += 4) {
        int sA = __ldg(&g_csr[s0 + e]);
        int sB = __ldg(&g_csr[s0 + e + 2]);
        int xA = __ldg(x + sA);
        int xB = __ldg(x + sB);
        float dA = __ldg(&g_dinv[sA]);
        float dB = __ldg(&g_dinv[sB]);
        float4 vA = ((const float4*)g_T1)[(size_t)xA * 16 + c];
        float4 vB = ((const float4*)g_T1)[(size_t)xB * 16 + c];
        acc0.x += dA * vA.x; acc0.y += dA * vA.y;
        acc0.z += dA * vA.z; acc0.w += dA * vA.w;
        acc1.x += dB * vB.x; acc1.y += dB * vB.y;
        acc1.z += dB * vB.z; acc1.w += dB * vB.w;
    }
    if (e < dg) {
        int s  = __ldg(&g_csr[s0 + e]);
        int xi = __ldg(x + s);
        float ds = __ldg(&g_dinv[s]);
        float4 v = ((const float4*)g_T1)[(size_t)xi * 16 + c];
        acc0.x += ds * v.x; acc0.y += ds * v.y;
        acc0.z += ds * v.z; acc0.w += ds * v.w;
    }
    float4 acc;
    acc.x = acc0.x + acc1.x; acc.y = acc0.y + acc1.y;
    acc.z = acc0.z + acc1.z; acc.w = acc0.w + acc1.w;

    acc.x += __shfl_down_sync(0xffffffffu, acc.x, 16);
    acc.y += __shfl_down_sync(0xffffffffu, acc.y, 16);
    acc.z += __shfl_down_sync(0xffffffffu, acc.z, 16);
    acc.w += __shfl_down_sync(0xffffffffu, acc.w, 16);

    if (half == 0) {
        float di = g_dinv[warp];
        int xi = __ldg(x + warp);
        float4 a  = ((const float4*)g_T1)[(size_t)xi * 16 + c];
        float4 bb = __ldg((const float4*)bias + c);
        float4 h;
        h.x = fmaxf(di * (di * a.x + acc.x) + bb.x, 0.f);
        h.y = fmaxf(di * (di * a.y + acc.y) + bb.y, 0.f);
        h.z = fmaxf(di * (di * a.z + acc.z) + bb.z, 0.f);
        h.w = fmaxf(di * (di * a.w + acc.w) + bb.w, 0.f);
        ((float4*)g_bufB)[(size_t)warp * 16 + c] = h;
    }
}

// ---------------- GEMM layer 2 (node tile [lo,hi)): A = dinv * (h @ W2) -----
// R7-validated internals: NT=4, 16 cols/thread, 2 blocks/SM. Do not reshape.
__global__ void __launch_bounds__(256, 2)
k_gemm2(const float* __restrict__ W, int lo, int hi) {
    __shared__ float4 Ws[D * 16];
    for (int t = threadIdx.x; t < D * 16; t += 256)
        Ws[t] = ((const float4*)W)[t];
    __syncthreads();

    int T    = blockIdx.x * 256 + threadIdx.x;
    int lane = threadIdx.x & 31;
    int q    = lane & 3;
    int r8   = lane >> 2;
    int wb   = lo + (T >> 5) * 32;

    int n[NT];
    const float4* hrow[NT];
    #pragma unroll
    for (int i = 0; i < NT; i++) {
        n[i] = wb + r8 + i * 8;
        int ns = (n[i] < hi) ? n[i] : lo;
        hrow[i] = (const float4*)g_bufB + (size_t)ns * 16;
    }

    unsigned long long acc2[NT][8];
    #pragma unroll
    for (int i = 0; i < NT; i++)
        #pragma unroll
        for (int j = 0; j < 8; j++) acc2[i][j] = 0ull;

    #pragma unroll 4
    for (int k4 = 0; k4 < 16; k4++) {
        float4 h[NT];
        #pragma unroll
        for (int i = 0; i < NT; i++) h[i] = hrow[i][k4];
        KSTEP2(0, x)
        KSTEP2(1, y)
        KSTEP2(2, z)
        KSTEP2(3, w)
    }

    #pragma unroll
    for (int i = 0; i < NT; i++) {
        if (n[i] >= hi) continue;
        unsigned long long di2 = pack2(g_dinv[n[i]]);
        ulonglong2* A = (ulonglong2*)((float4*)g_bufA + (size_t)n[i] * 16 + q * 4);
        #pragma unroll
        for (int j = 0; j < 4; j++) {
            mul2(acc2[i][2 * j],     di2);
            mul2(acc2[i][2 * j + 1], di2);
            A[j] = make_ulonglong2(acc2[i][2 * j], acc2[i][2 * j + 1]);
        }
    }
}

// ------- gather layer 2 + pool: gsum[b] += relu(dinv*(A_i+agg)+b2) ----------
__global__ void __launch_bounds__(256)
k_gather2(const int* __restrict__ batch, const float* __restrict__ bias) {
    int warp = (blockIdx.x * blockDim.x + threadIdx.x) >> 5;
    if (warp >= N_NODES) return;
    int lane = threadIdx.x & 31;
    int half = lane >> 4;
    int c    = lane & 15;

    int s0 = g_start[warp];
    int dg = g_deg[warp];

    float4 acc0 = make_float4(0.f, 0.f, 0.f, 0.f);
    float4 acc1 = make_float4(0.f, 0.f, 0.f, 0.f);
    int e = half;
    for (; e + 2 < dg; e += 4) {
        int sA = __ldg(&g_csr[s0 + e]);
        int sB = __ldg(&g_csr[s0 + e + 2]);
        float4 vA = ((const float4*)g_bufA)[(size_t)sA * 16 + c];
        float4 vB = ((const float4*)g_bufA)[(size_t)sB * 16 + c];
        acc0.x += vA.x; acc0.y += vA.y; acc0.z += vA.z; acc0.w += vA.w;
        acc1.x += vB.x; acc1.y += vB.y; acc1.z += vB.z; acc1.w += vB.w;
    }
    if (e < dg) {
        int s = __ldg(&g_csr[s0 + e]);
        float4 v = ((const float4*)g_bufA)[(size_t)s * 16 + c];
        acc0.x += v.x; acc0.y += v.y; acc0.z += v.z; acc0.w += v.w;
    }
    float4 acc;
    acc.x = acc0.x + acc1.x; acc.y = acc0.y + acc1.y;
    acc.z = acc0.z + acc1.z; acc.w = acc0.w + acc1.w;

    acc.x += __shfl_down_sync(0xffffffffu, acc.x, 16);
    acc.y += __shfl_down_sync(0xffffffffu, acc.y, 16);
    acc.z += __shfl_down_sync(0xffffffffu, acc.z, 16);
    acc.w += __shfl_down_sync(0xffffffffu, acc.w, 16);

    if (half == 0) {
        float di = g_dinv[warp];
        int b = __ldg(batch + warp);
        float4 a  = ((const float4*)g_bufA)[(size_t)warp * 16 + c];
        float4 bb = __ldg((const float4*)bias + c);
        float4 v;
        v.x = fmaxf(di * (a.x + acc.x) + bb.x, 0.f);
        v.y = fmaxf(di * (a.y + acc.y) + bb.y, 0.f);
        v.z = fmaxf(di * (a.z + acc.z) + bb.z, 0.f);
        v.w = fmaxf(di * (a.w + acc.w) + bb.w, 0.f);
        red_add_v4(&g_gsum[b * D + c * 4], v);
        if (c == 0) atomicAdd(&g_gcnt[b], 1.0f);
    }
}

// ---------------- head: out[g] = (gsum[g]/cnt) @ Wlin + blin ----------------
__global__ void k_final(const float* __restrict__ Wlin,
                        const float* __restrict__ blin,
                        float* __restrict__ out) {
    int g = blockIdx.x * blockDim.x + threadIdx.x;
    if (g >= NUM_GRAPHS) return;
    float inv = 1.0f / fmaxf(g_gcnt[g], 1.0f);
    float a0 = blin[0], a1 = blin[1];
    #pragma unroll
    for (int j = 0; j < D; j++) {
        float v = g_gsum[g * D + j] * inv;
        a0 += v * Wlin[2 * j + 0];
        a1 += v * Wlin[2 * j + 1];
    }
    out[2 * g + 0] = a0;
    out[2 * g + 1] = a1;
}

// ---------------- launch ----------------------------------------------------
extern "C" void kernel_launch(void* const* d_in, const int* in_sizes, int n_in,
                              void* d_out, int out_size) {
    const int*   x     = (const int*)  d_in[0];
    const int*   ei    = (const int*)  d_in[1];
    const int*   batch = (const int*)  d_in[3];
    const float* table = (const float*)d_in[4];
    const float* W1    = (const float*)d_in[5];
    const float* b1    = (const float*)d_in[6];
    const float* W2    = (const float*)d_in[7];
    const float* b2    = (const float*)d_in[8];
    const float* Wlin  = (const float*)d_in[9];
    const float* blin  = (const float*)d_in[10];
    float*       out   = (float*)d_out;

    int E = in_sizes[1] / 2;
    const int* src = ei;       // edge_index[0]
    const int* dst = ei + E;   // edge_index[1]

    const int TPB = 256;
    int gbN = (N_NODES + TPB - 1) / TPB;                         // 782
    int gbE = (E + TPB - 1) / TPB;
    int gbW = (int)(((long long)N_NODES * 32 + TPB - 1) / TPB);  // warp/node
    int gbV = (VOCAB + TPB - 1) / TPB;                           // 40
    int gbWt = (int)(((long long)TILE * 32 + TPB - 1) / TPB);    // 6250 (g1 tile)
    int gbGt = (TILE + TPB - 1) / TPB;                           // 196 (gemm2 tile)

    cudaStream_t s2;
    cudaEvent_t evFork, evJoin, evG[NTILE], evT;
    cudaStreamCreateWithFlags(&s2, cudaStreamNonBlocking);
    cudaEventCreateWithFlags(&evFork, cudaEventDisableTiming);
    cudaEventCreateWithFlags(&evJoin, cudaEventDisableTiming);
    for (int q = 0; q < NTILE; q++)
        cudaEventCreateWithFlags(&evG[q], cudaEventDisableTiming);
    cudaEventCreateWithFlags(&evT, cudaEventDisableTiming);

    cudaEventRecord(evFork, 0);
    cudaStreamWaitEvent(s2, evFork, 0);

    // branch A (s2): CSR build + dinv
    k_init<<<gbN, TPB, 0, s2>>>();
    k_deg<<<gbE, TPB, 0, s2>>>(dst, E);
    k_scan1<<<NB_SCAN, SCAN_B, 0, s2>>>();
    k_scan2<<<1, 1024, 0, s2>>>();
    k_scan3<<<NB_SCAN, SCAN_B, 0, s2>>>();
    k_fill<<<gbE, TPB, 0, s2>>>(src, dst, E);

    // branch B (main stream): tiny vocab-level transform
    k_t1<<<gbV, TPB>>>(table, W1);                 // T1 = table @ W1

    // join: CSR done before gather1 tiles
    cudaEventRecord(evJoin, s2);
    cudaStreamWaitEvent(0, evJoin, 0);

    // Software pipeline: gather1 tiles on stream 0, gemm2 tiles on s2,
    // each gemm2 tile gated on its gather1 tile's event.
    for (int q = 0; q < NTILE; q++) {
        int lo = q * TILE;
        int hi = (q == NTILE - 1) ? N_NODES : lo + TILE;
        k_gather1<<<gbWt, TPB>>>(x, b1, lo, hi);
        cudaEventRecord(evG[q], 0);
        cudaStreamWaitEvent(s2, evG[q], 0);
        k_gemm2<<<gbGt, TPB, 0, s2>>>(W2, lo, hi);
    }

    // gather2 needs full bufA: gate on last gemm2 tile (s2 is in-order).
    cudaEventRecord(evT, s2);
    cudaStreamWaitEvent(0, evT, 0);

    k_gather2<<<gbW, TPB>>>(batch, b2);            // gsum += relu(dinv*(A_i+ΣA_s)+b2)
    k_final<<<(NUM_GRAPHS + TPB - 1) / TPB, TPB>>>(Wlin, blin, out);

    cudaEventDestroy(evFork);
    cudaEventDestroy(evJoin);
    for (int q = 0; q < NTILE; q++) cudaEventDestroy(evG[q]);
    cudaEventDestroy(evT);
    cudaStreamDestroy(s2);
}

// round 14
// speedup vs baseline: 1.2538x; 1.0530x over previous
#include <cuda_runtime.h>
#include <cuda_bf16.h>
#include <cuda_fp16.h>

#define N_NODES    200000
#define NUM_GRAPHS 2000
#define VOCAB      10000
#define D          64
#define NT         4     // nodes per thread (gemm kernels)
#define MAX_E      1600000
#define SCAN_B     256
#define NB_SCAN    ((N_NODES + SCAN_B - 1) / SCAN_B)   // 782

// ---------------- scratch (static device globals; no allocation) ------------
__device__ __half g_T1h [(size_t)VOCAB * D];    // embed_table @ W1 (fp16 storage)
__device__ __half g_bufAh[(size_t)N_NODES * D]; // layer-2 ts (fp16 storage)
__device__ float  g_bufB[(size_t)N_NODES * D];  // h (layer-1 activations, fp32)
__device__ float  g_dinv[N_NODES];
__device__ int    g_deg [N_NODES];
__device__ int    g_start[N_NODES];             // CSR row offsets (by dst)
__device__ int    g_cursor[N_NODES];
__device__ int    g_csr[MAX_E];                 // src indices bucketed by dst
__device__ int    g_bsum[NB_SCAN];
__device__ float  g_gsum[NUM_GRAPHS * D];
__device__ float  g_gcnt[NUM_GRAPHS];

// vectorized no-return global reduction (sm_90+)
__device__ __forceinline__ void red_add_v4(float* addr, float4 v) {
    asm volatile("red.global.add.v4.f32 [%0], {%1, %2, %3, %4};"
                 :: "l"(addr), "f"(v.x), "f"(v.y), "f"(v.z), "f"(v.w)
                 : "memory");
}

// ---------------- packed f32x2 helpers (sm_103a FFMA2 path) -----------------
__device__ __forceinline__ unsigned long long pack2(float v) {
    unsigned long long r;
    asm("mov.b64 %0, {%1, %1};" : "=l"(r) : "f"(v));
    return r;
}
__device__ __forceinline__ void ffma2(unsigned long long& d,
                                      unsigned long long a,
                                      unsigned long long b) {
    asm("fma.rn.f32x2 %0, %1, %2, %0;" : "+l"(d) : "l"(a), "l"(b));
}
__device__ __forceinline__ void mul2(unsigned long long& d,
                                     unsigned long long a) {
    asm("mul.rn.f32x2 %0, %0, %1;" : "+l"(d) : "l"(a));
}

// ---------------- fp16 payload helpers --------------------------------------
// 8 bytes = 4 halves -> 4 floats (cols c*4 .. c*4+3 of a 64-col row)
__device__ __forceinline__ float4 h4_to_f4(unsigned long long v) {
    union { unsigned long long u; __half2 h[2]; } cv;
    cv.u = v;
    float2 f0 = __half22float2(cv.h[0]);
    float2 f1 = __half22float2(cv.h[1]);
    return make_float4(f0.x, f0.y, f1.x, f1.y);
}
// packed f32x2 -> half2 (as u32)
__device__ __forceinline__ unsigned int f32x2_to_h2(unsigned long long p) {
    union { unsigned long long u; float f[2]; } cv;
    cv.u = p;
    __half2 h = __float22half2_rn(make_float2(cv.f[0], cv.f[1]));
    return *reinterpret_cast<unsigned int*>(&h);
}

// ---------------- init: zero deg / gsum / gcnt ------------------------------
__global__ void k_init() {
    int t = blockIdx.x * blockDim.x + threadIdx.x;
    if (t < N_NODES)        g_deg[t]  = 0;
    if (t < NUM_GRAPHS * D) g_gsum[t] = 0.0f;
    if (t < NUM_GRAPHS)     g_gcnt[t] = 0.0f;
}

// ---------------- degree (in-degree over dst) -------------------------------
__global__ void k_deg(const int* __restrict__ dst, int E) {
    int e = blockIdx.x * blockDim.x + threadIdx.x;
    if (e < E) atomicAdd(&g_deg[dst[e]], 1);
}

// ---------------- CSR build: scan + fill ------------------------------------
__global__ void k_scan1() {
    __shared__ int s[SCAN_B];
    int tid = threadIdx.x;
    int t = blockIdx.x * SCAN_B + tid;
    int v = (t < N_NODES) ? g_deg[t] : 0;
    s[tid] = v;
    __syncthreads();
    #pragma unroll
    for (int o = 1; o < SCAN_B; o <<= 1) {
        int u = (tid >= o) ? s[tid - o] : 0;
        __syncthreads();
        s[tid] += u;
        __syncthreads();
    }
    if (t < N_NODES) g_start[t] = s[tid] - v;     // exclusive
    if (tid == SCAN_B - 1) g_bsum[blockIdx.x] = s[tid];
}

__global__ void k_scan2() {
    __shared__ int s[1024];
    int tid = threadIdx.x;
    int v = (tid < NB_SCAN) ? g_bsum[tid] : 0;
    s[tid] = v;
    __syncthreads();
    #pragma unroll
    for (int o = 1; o < 1024; o <<= 1) {
        int u = (tid >= o) ? s[tid - o] : 0;
        __syncthreads();
        s[tid] += u;
        __syncthreads();
    }
    if (tid < NB_SCAN) g_bsum[tid] = s[tid] - v;  // exclusive block offsets
}

__global__ void k_scan3() {
    int t = blockIdx.x * blockDim.x + threadIdx.x;
    if (t >= N_NODES) return;
    int st = g_start[t] + g_bsum[blockIdx.x];
    g_start[t]  = st;
    g_cursor[t] = st;
    g_dinv[t]   = rsqrtf((float)(g_deg[t] + 1));  // +1 self loop
}

__global__ void k_fill(const int* __restrict__ src, const int* __restrict__ dst, int E) {
    int e = blockIdx.x * blockDim.x + threadIdx.x;
    if (e >= E) return;
    int d = dst[e];
    int pos = atomicAdd(&g_cursor[d], 1);
    g_csr[pos] = src[e];
}

// FFMA2 k-slice, 16 cols/thread
#define KSTEP2(R, COMP)                                                       \
    {                                                                         \
        const ulonglong2* wr =                                                \
            (const ulonglong2*)&Ws[(k4 * 4 + (R)) * 16 + q * 4];              \
        ulonglong2 wv0 = wr[0], wv1 = wr[1], wv2 = wr[2], wv3 = wr[3];        \
        _Pragma("unroll")                                                     \
        for (int i = 0; i < NT; i++) {                                        \
            unsigned long long hs2 = pack2(h[i].COMP);                        \
            ffma2(acc2[i][0], hs2, wv0.x);                                    \
            ffma2(acc2[i][1], hs2, wv0.y);                                    \
            ffma2(acc2[i][2], hs2, wv1.x);                                    \
            ffma2(acc2[i][3], hs2, wv1.y);                                    \
            ffma2(acc2[i][4], hs2, wv2.x);                                    \
            ffma2(acc2[i][5], hs2, wv2.y);                                    \
            ffma2(acc2[i][6], hs2, wv3.x);                                    \
            ffma2(acc2[i][7], hs2, wv3.y);                                    \
        }                                                                     \
    }

// ---------------- T1 = embed_table @ W1  (VOCAB x 64, fp16 out) -------------
__global__ void __launch_bounds__(256, 2)
k_t1(const float* __restrict__ table, const float* __restrict__ W) {
    __shared__ float4 Ws[D * 16];   // W row-major: Ws[k*16 + j4]
    for (int t = threadIdx.x; t < D * 16; t += 256)
        Ws[t] = ((const float4*)W)[t];
    __syncthreads();

    int T    = blockIdx.x * 256 + threadIdx.x;
    int lane = threadIdx.x & 31;
    int q    = lane & 3;
    int r8   = lane >> 2;
    int wb   = (T >> 5) * 32;

    int n[NT];
    const float4* hrow[NT];
    #pragma unroll
    for (int i = 0; i < NT; i++) {
        n[i] = wb + r8 + i * 8;
        int ns = (n[i] < VOCAB) ? n[i] : 0;
        hrow[i] = (const float4*)(table + (size_t)ns * D);
    }

    unsigned long long acc2[NT][8];
    #pragma unroll
    for (int i = 0; i < NT; i++)
        #pragma unroll
        for (int j = 0; j < 8; j++) acc2[i][j] = 0ull;

    #pragma unroll 4
    for (int k4 = 0; k4 < 16; k4++) {
        float4 h[NT];
        #pragma unroll
        for (int i = 0; i < NT; i++) h[i] = hrow[i][k4];
        KSTEP2(0, x)
        KSTEP2(1, y)
        KSTEP2(2, z)
        KSTEP2(3, w)
    }

    #pragma unroll
    for (int i = 0; i < NT; i++) {
        if (n[i] >= VOCAB) continue;
        uint4* O = (uint4*)(g_T1h + (size_t)n[i] * D) + q * 2;
        O[0] = make_uint4(f32x2_to_h2(acc2[i][0]), f32x2_to_h2(acc2[i][1]),
                          f32x2_to_h2(acc2[i][2]), f32x2_to_h2(acc2[i][3]));
        O[1] = make_uint4(f32x2_to_h2(acc2[i][4]), f32x2_to_h2(acc2[i][5]),
                          f32x2_to_h2(acc2[i][6]), f32x2_to_h2(acc2[i][7]));
    }
}

// ---- gather layer 1: h = relu(di*(di*T1[x_i] + Σ dinv[s]*T1[x[s]]) + b1) ---
// One warp per node; manual 2-way software pipelining (R10-validated).
// Rows are fp16 (8 B per lane), accumulation in fp32.
__global__ void __launch_bounds__(256)
k_gather1(const int* __restrict__ x, const float* __restrict__ bias) {
    int warp = (blockIdx.x * blockDim.x + threadIdx.x) >> 5;
    if (warp >= N_NODES) return;
    int lane = threadIdx.x & 31;
    int half = lane >> 4;
    int c    = lane & 15;

    int s0 = g_start[warp];
    int dg = g_deg[warp];

    float4 acc0 = make_float4(0.f, 0.f, 0.f, 0.f);
    float4 acc1 = make_float4(0.f, 0.f, 0.f, 0.f);
    int e = half;
    for (; e + 2 < dg; e += 4) {
        int sA = __ldg(&g_csr[s0 + e]);
        int sB = __ldg(&g_csr[s0 + e + 2]);
        int xA = __ldg(x + sA);
        int xB = __ldg(x + sB);
        float dA = __ldg(&g_dinv[sA]);
        float dB = __ldg(&g_dinv[sB]);
        unsigned long long rA =
            ((const unsigned long long*)(g_T1h + (size_t)xA * D))[c];
        unsigned long long rB =
            ((const unsigned long long*)(g_T1h + (size_t)xB * D))[c];
        float4 vA = h4_to_f4(rA);
        float4 vB = h4_to_f4(rB);
        acc0.x += dA * vA.x; acc0.y += dA * vA.y;
        acc0.z += dA * vA.z; acc0.w += dA * vA.w;
        acc1.x += dB * vB.x; acc1.y += dB * vB.y;
        acc1.z += dB * vB.z; acc1.w += dB * vB.w;
    }
    if (e < dg) {
        int s  = __ldg(&g_csr[s0 + e]);
        int xi = __ldg(x + s);
        float ds = __ldg(&g_dinv[s]);
        float4 v = h4_to_f4(
            ((const unsigned long long*)(g_T1h + (size_t)xi * D))[c]);
        acc0.x += ds * v.x; acc0.y += ds * v.y;
        acc0.z += ds * v.z; acc0.w += ds * v.w;
    }
    float4 acc;
    acc.x = acc0.x + acc1.x; acc.y = acc0.y + acc1.y;
    acc.z = acc0.z + acc1.z; acc.w = acc0.w + acc1.w;

    acc.x += __shfl_down_sync(0xffffffffu, acc.x, 16);
    acc.y += __shfl_down_sync(0xffffffffu, acc.y, 16);
    acc.z += __shfl_down_sync(0xffffffffu, acc.z, 16);
    acc.w += __shfl_down_sync(0xffffffffu, acc.w, 16);

    if (half == 0) {
        float di = g_dinv[warp];
        int xi = __ldg(x + warp);
        float4 a = h4_to_f4(
            ((const unsigned long long*)(g_T1h + (size_t)xi * D))[c]);
        float4 bb = __ldg((const float4*)bias + c);
        float4 h;
        h.x = fmaxf(di * (di * a.x + acc.x) + bb.x, 0.f);
        h.y = fmaxf(di * (di * a.y + acc.y) + bb.y, 0.f);
        h.z = fmaxf(di * (di * a.z + acc.z) + bb.z, 0.f);
        h.w = fmaxf(di * (di * a.w + acc.w) + bb.w, 0.f);
        ((float4*)g_bufB)[(size_t)warp * 16 + c] = h;
    }
}

// ---------------- GEMM layer 2: A = dinv * (h @ W2),  h = bufB --------------
// R7-validated internals (NT=4, 16 cols/thread, 2 blocks/SM); only the
// epilogue store changes (fp16 out).
__global__ void __launch_bounds__(256, 2)
k_gemm2(const float* __restrict__ W) {
    __shared__ float4 Ws[D * 16];
    for (int t = threadIdx.x; t < D * 16; t += 256)
        Ws[t] = ((const float4*)W)[t];
    __syncthreads();

    int T    = blockIdx.x * 256 + threadIdx.x;
    int lane = threadIdx.x & 31;
    int q    = lane & 3;
    int r8   = lane >> 2;
    int wb   = (T >> 5) * 32;

    int n[NT];
    const float4* hrow[NT];
    #pragma unroll
    for (int i = 0; i < NT; i++) {
        n[i] = wb + r8 + i * 8;
        int ns = (n[i] < N_NODES) ? n[i] : 0;
        hrow[i] = (const float4*)g_bufB + (size_t)ns * 16;
    }

    unsigned long long acc2[NT][8];
    #pragma unroll
    for (int i = 0; i < NT; i++)
        #pragma unroll
        for (int j = 0; j < 8; j++) acc2[i][j] = 0ull;

    #pragma unroll 4
    for (int k4 = 0; k4 < 16; k4++) {
        float4 h[NT];
        #pragma unroll
        for (int i = 0; i < NT; i++) h[i] = hrow[i][k4];
        KSTEP2(0, x)
        KSTEP2(1, y)
        KSTEP2(2, z)
        KSTEP2(3, w)
    }

    #pragma unroll
    for (int i = 0; i < NT; i++) {
        if (n[i] >= N_NODES) continue;
        unsigned long long di2 = pack2(g_dinv[n[i]]);
        #pragma unroll
        for (int j = 0; j < 8; j++) mul2(acc2[i][j], di2);
        uint4* A = (uint4*)(g_bufAh + (size_t)n[i] * D) + q * 2;
        A[0] = make_uint4(f32x2_to_h2(acc2[i][0]), f32x2_to_h2(acc2[i][1]),
                          f32x2_to_h2(acc2[i][2]), f32x2_to_h2(acc2[i][3]));
        A[1] = make_uint4(f32x2_to_h2(acc2[i][4]), f32x2_to_h2(acc2[i][5]),
                          f32x2_to_h2(acc2[i][6]), f32x2_to_h2(acc2[i][7]));
    }
}

// ------- gather layer 2 + pool: gsum[b] += relu(dinv*(A_i+agg)+b2) ----------
// Rows are fp16 (8 B per lane), accumulation in fp32.
__global__ void __launch_bounds__(256)
k_gather2(const int* __restrict__ batch, const float* __restrict__ bias) {
    int warp = (blockIdx.x * blockDim.x + threadIdx.x) >> 5;
    if (warp >= N_NODES) return;
    int lane = threadIdx.x & 31;
    int half = lane >> 4;
    int c    = lane & 15;

    int s0 = g_start[warp];
    int dg = g_deg[warp];

    float4 acc0 = make_float4(0.f, 0.f, 0.f, 0.f);
    float4 acc1 = make_float4(0.f, 0.f, 0.f, 0.f);
    int e = half;
    for (; e + 2 < dg; e += 4) {
        int sA = __ldg(&g_csr[s0 + e]);
        int sB = __ldg(&g_csr[s0 + e + 2]);
        unsigned long long rA =
            ((const unsigned long long*)(g_bufAh + (size_t)sA * D))[c];
        unsigned long long rB =
            ((const unsigned long long*)(g_bufAh + (size_t)sB * D))[c];
        float4 vA = h4_to_f4(rA);
        float4 vB = h4_to_f4(rB);
        acc0.x += vA.x; acc0.y += vA.y; acc0.z += vA.z; acc0.w += vA.w;
        acc1.x += vB.x; acc1.y += vB.y; acc1.z += vB.z; acc1.w += vB.w;
    }
    if (e < dg) {
        int s = __ldg(&g_csr[s0 + e]);
        float4 v = h4_to_f4(
            ((const unsigned long long*)(g_bufAh + (size_t)s * D))[c]);
        acc0.x += v.x; acc0.y += v.y; acc0.z += v.z; acc0.w += v.w;
    }
    float4 acc;
    acc.x = acc0.x + acc1.x; acc.y = acc0.y + acc1.y;
    acc.z = acc0.z + acc1.z; acc.w = acc0.w + acc1.w;

    acc.x += __shfl_down_sync(0xffffffffu, acc.x, 16);
    acc.y += __shfl_down_sync(0xffffffffu, acc.y, 16);
    acc.z += __shfl_down_sync(0xffffffffu, acc.z, 16);
    acc.w += __shfl_down_sync(0xffffffffu, acc.w, 16);

    if (half == 0) {
        float di = g_dinv[warp];
        int b = __ldg(batch + warp);
        float4 a = h4_to_f4(
            ((const unsigned long long*)(g_bufAh + (size_t)warp * D))[c]);
        float4 bb = __ldg((const float4*)bias + c);
        float4 v;
        v.x = fmaxf(di * (a.x + acc.x) + bb.x, 0.f);
        v.y = fmaxf(di * (a.y + acc.y) + bb.y, 0.f);
        v.z = fmaxf(di * (a.z + acc.z) + bb.z, 0.f);
        v.w = fmaxf(di * (a.w + acc.w) + bb.w, 0.f);
        red_add_v4(&g_gsum[b * D + c * 4], v);
        if (c == 0) atomicAdd(&g_gcnt[b], 1.0f);
    }
}

// ---------------- head: out[g] = (gsum[g]/cnt) @ Wlin + blin ----------------
__global__ void k_final(const float* __restrict__ Wlin,
                        const float* __restrict__ blin,
                        float* __restrict__ out) {
    int g = blockIdx.x * blockDim.x + threadIdx.x;
    if (g >= NUM_GRAPHS) return;
    float inv = 1.0f / fmaxf(g_gcnt[g], 1.0f);
    float a0 = blin[0], a1 = blin[1];
    #pragma unroll
    for (int j = 0; j < D; j++) {
        float v = g_gsum[g * D + j] * inv;
        a0 += v * Wlin[2 * j + 0];
        a1 += v * Wlin[2 * j + 1];
    }
    out[2 * g + 0] = a0;
    out[2 * g + 1] = a1;
}

// ---------------- launch ----------------------------------------------------
extern "C" void kernel_launch(void* const* d_in, const int* in_sizes, int n_in,
                              void* d_out, int out_size) {
    const int*   x     = (const int*)  d_in[0];
    const int*   ei    = (const int*)  d_in[1];
    const int*   batch = (const int*)  d_in[3];
    const float* table = (const float*)d_in[4];
    const float* W1    = (const float*)d_in[5];
    const float* b1    = (const float*)d_in[6];
    const float* W2    = (const float*)d_in[7];
    const float* b2    = (const float*)d_in[8];
    const float* Wlin  = (const float*)d_in[9];
    const float* blin  = (const float*)d_in[10];
    float*       out   = (float*)d_out;

    int E = in_sizes[1] / 2;
    const int* src = ei;       // edge_index[0]
    const int* dst = ei + E;   // edge_index[1]

    const int TPB = 256;
    int gbN = (N_NODES + TPB - 1) / TPB;                         // 782
    int gbE = (E + TPB - 1) / TPB;
    int gbW = (int)(((long long)N_NODES * 32 + TPB - 1) / TPB);  // warp/node
    int gbV = (VOCAB + TPB - 1) / TPB;                           // 40

    // Fork a second branch for the CSR build (independent of T1).
    cudaStream_t s2;
    cudaEvent_t evFork, evJoin;
    cudaStreamCreateWithFlags(&s2, cudaStreamNonBlocking);
    cudaEventCreateWithFlags(&evFork, cudaEventDisableTiming);
    cudaEventCreateWithFlags(&evJoin, cudaEventDisableTiming);

    cudaEventRecord(evFork, 0);
    cudaStreamWaitEvent(s2, evFork, 0);

    // branch A (s2): CSR build + dinv
    k_init<<<gbN, TPB, 0, s2>>>();
    k_deg<<<gbE, TPB, 0, s2>>>(dst, E);
    k_scan1<<<NB_SCAN, SCAN_B, 0, s2>>>();
    k_scan2<<<1, 1024, 0, s2>>>();
    k_scan3<<<NB_SCAN, SCAN_B, 0, s2>>>();
    k_fill<<<gbE, TPB, 0, s2>>>(src, dst, E);

    // branch B (main stream): tiny vocab-level transform
    k_t1<<<gbV, TPB>>>(table, W1);                 // T1h = table @ W1 (fp16)

    // join
    cudaEventRecord(evJoin, s2);
    cudaStreamWaitEvent(0, evJoin, 0);

    k_gather1<<<gbW, TPB>>>(x, b1);                // B = relu(di*(di*T1[x_i]+Σ ds*T1[xs])+b1)
    k_gemm2<<<gbN, TPB>>>(W2);                     // Ah = dinv*(B@W2)  (fp16 out)
    k_gather2<<<gbW, TPB>>>(batch, b2);            // gsum += relu(dinv*(A_i+ΣA_s)+b2)
    k_final<<<(NUM_GRAPHS + TPB - 1) / TPB, TPB>>>(Wlin, blin, out);

    cudaEventDestroy(evFork);
    cudaEventDestroy(evJoin);
    cudaStreamDestroy(s2);
}